// round 14
// baseline (speedup 1.0000x reference)
#include <cuda_runtime.h>
#include <cuda_bf16.h>

#define DD 4096
#define NSM 148
#define THREADS 1024          // 32 warps, one block per SM
#define MATSZ ((size_t)DD * DD)

// ping-pong node buffers (scatter idx is a permutation -> fully overwritten each layer)
__device__ float g_buf0[DD];
__device__ float g_buf1[DD];

// streaming float4 load: no L1 allocation, 256B L2 fetch granule (HBM3e-friendly)
__device__ __forceinline__ float4 ldg_stream(const float4* p) {
    float4 v;
    asm volatile("ld.global.nc.L1::no_allocate.L2::256B.v4.f32 {%0,%1,%2,%3}, [%4];"
                 : "=f"(v.x), "=f"(v.y), "=f"(v.z), "=f"(v.w) : "l"(p));
    return v;
}

template<bool MASK, bool GATHER, bool SCATTER>
__global__ void __launch_bounds__(THREADS, 1)
gemv_layer(const float* __restrict__ W,
           const float* __restrict__ O,
           const float* __restrict__ bias,
           const float* __restrict__ src,
           const int*   __restrict__ gidx,
           const int*   __restrict__ sidx,
           float*       __restrict__ dst)
{
    __shared__ float s_in[DD];

    const int t = threadIdx.x;
    // gather the input vector into smem; indices via one int4 load per thread
    if (GATHER) {
        const int4 gi = __ldg(reinterpret_cast<const int4*>(gidx) + t);
        float tmp0 = __ldg(src + gi.x);
        float tmp1 = __ldg(src + gi.y);
        float tmp2 = __ldg(src + gi.z);
        float tmp3 = __ldg(src + gi.w);
        s_in[4 * t + 0] = tmp0;
        s_in[4 * t + 1] = tmp1;
        s_in[4 * t + 2] = tmp2;
        s_in[4 * t + 3] = tmp3;
    } else {
        #pragma unroll
        for (int j = t; j < DD; j += THREADS) s_in[j] = __ldg(src + j);
    }
    __syncthreads();

    // static balanced row partition: block b owns [b*DD/NSM, (b+1)*DD/NSM)
    const int r_start = (int)(((long long)blockIdx.x * DD) / NSM);
    const int r_end   = (int)(((long long)(blockIdx.x + 1) * DD) / NSM);

    const int lane = t & 31;
    const int w    = t >> 5;
    const int row  = r_start + w;
    if (row >= r_end) return;   // surplus warps exit after helping the gather

    const float4* __restrict__ w4 = reinterpret_cast<const float4*>(W + (size_t)row * DD) + lane;
    const float4* __restrict__ s4 = reinterpret_cast<const float4*>(s_in) + lane;

    float acc0 = 0.f, acc1 = 0.f;

    if (MASK) {
        constexpr int UF = 4;                       // 4 W + 4 O float4 buffers in flight
        const float4* __restrict__ o4 = reinterpret_cast<const float4*>(O + (size_t)row * DD) + lane;
        float4 wb[UF], ob[UF];
        #pragma unroll
        for (int base = 0; base < 32; base += UF) {
            #pragma unroll
            for (int u = 0; u < UF; ++u) wb[u] = ldg_stream(w4 + (base + u) * 32);
            #pragma unroll
            for (int u = 0; u < UF; ++u) ob[u] = ldg_stream(o4 + (base + u) * 32);
            #pragma unroll
            for (int u = 0; u < UF; ++u) {
                const float4 xi = s4[(base + u) * 32];
                acc0 = fmaf(wb[u].x * ob[u].x, xi.x, acc0);
                acc1 = fmaf(wb[u].y * ob[u].y, xi.y, acc1);
                acc0 = fmaf(wb[u].z * ob[u].z, xi.z, acc0);
                acc1 = fmaf(wb[u].w * ob[u].w, xi.w, acc1);
            }
        }
    } else {
        constexpr int UF = 8;                       // 8 W float4 buffers in flight
        float4 wb[UF];
        #pragma unroll
        for (int base = 0; base < 32; base += UF) {
            #pragma unroll
            for (int u = 0; u < UF; ++u) wb[u] = ldg_stream(w4 + (base + u) * 32);
            #pragma unroll
            for (int u = 0; u < UF; ++u) {
                const float4 xi = s4[(base + u) * 32];
                acc0 = fmaf(wb[u].x, xi.x, acc0);
                acc1 = fmaf(wb[u].y, xi.y, acc1);
                acc0 = fmaf(wb[u].z, xi.z, acc0);
                acc1 = fmaf(wb[u].w, xi.w, acc1);
            }
        }
    }

    float acc = acc0 + acc1;
    // warp tree-reduce
    #pragma unroll
    for (int off = 16; off; off >>= 1)
        acc += __shfl_down_sync(0xffffffffu, acc, off);

    if (lane == 0) {
        float v = fmaxf(acc + __ldg(bias + row), 0.f);
        if (SCATTER) dst[__ldg(sidx + row)] = v;
        else         dst[row] = v;
    }
}

extern "C" void kernel_launch(void* const* d_in, const int* in_sizes, int n_in,
                              void* d_out, int out_size)
{
    const float* x       = (const float*)d_in[0];   // [D]
    const float* W_in    = (const float*)d_in[1];   // [D, D]
    const float* b_in    = (const float*)d_in[2];   // [D]
    const float* weights = (const float*)d_in[3];   // [L, D, D]
    const float* orders  = (const float*)d_in[4];   // [L, D, D]
    const float* biases  = (const float*)d_in[5];   // [L, D]
    const int*   gidx    = (const int*)d_in[6];     // [L, D]
    const int*   sidx    = (const int*)d_in[7];     // [L+1, D]
    float*       out     = (float*)d_out;           // [D]

    float *b0 = nullptr, *b1 = nullptr;
    cudaGetSymbolAddress((void**)&b0, g_buf0);
    cudaGetSymbolAddress((void**)&b1, g_buf1);

    dim3 grid(NSM), blk(THREADS);

    // input layer: relu(W_in @ x + b_in), scattered via scatter_idx[0]
    gemv_layer<false, false, true><<<grid, blk>>>(
        W_in, nullptr, b_in, x, nullptr, sidx, b0);

    // layer 0: gather g[0], masked GEMV, scatter s[1]
    gemv_layer<true, true, true><<<grid, blk>>>(
        weights, orders, biases, b0, gidx, sidx + DD, b1);

    // layer 1
    gemv_layer<true, true, true><<<grid, blk>>>(
        weights + MATSZ, orders + MATSZ, biases + DD, b1, gidx + DD, sidx + 2 * DD, b0);

    // layer 2
    gemv_layer<true, true, true><<<grid, blk>>>(
        weights + 2 * MATSZ, orders + 2 * MATSZ, biases + 2 * DD, b0, gidx + 2 * DD, sidx + 3 * DD, b1);

    // layer 3: final layer — output is the PRE-scatter activation, straight to d_out
    gemv_layer<true, true, false><<<grid, blk>>>(
        weights + 3 * MATSZ, orders + 3 * MATSZ, biases + 3 * DD, b1, gidx + 3 * DD, nullptr, out);
}

// round 15
// speedup vs baseline: 1.0450x; 1.0450x over previous
#include <cuda_runtime.h>
#include <cuda_bf16.h>

#define DD 4096
#define NSM 152               // GB300: 152 SMs (B300_MICROARCH, HW-measured)
#define THREADS 1024          // 32 warps, one block per SM
#define MATSZ ((size_t)DD * DD)

// ping-pong node buffers (scatter idx is a permutation -> fully overwritten each layer)
__device__ float g_buf0[DD];
__device__ float g_buf1[DD];

template<bool MASK, bool GATHER, bool SCATTER>
__global__ void __launch_bounds__(THREADS, 1)
gemv_layer(const float* __restrict__ W,
           const float* __restrict__ O,
           const float* __restrict__ bias,
           const float* __restrict__ src,
           const int*   __restrict__ gidx,
           const int*   __restrict__ sidx,
           float*       __restrict__ dst)
{
    __shared__ float s_in[DD];

    const int t = threadIdx.x;
    // gather the input vector into smem; indices via one int4 load per thread
    if (GATHER) {
        const int4 gi = __ldg(reinterpret_cast<const int4*>(gidx) + t);
        float tmp0 = __ldg(src + gi.x);
        float tmp1 = __ldg(src + gi.y);
        float tmp2 = __ldg(src + gi.z);
        float tmp3 = __ldg(src + gi.w);
        s_in[4 * t + 0] = tmp0;
        s_in[4 * t + 1] = tmp1;
        s_in[4 * t + 2] = tmp2;
        s_in[4 * t + 3] = tmp3;
    } else {
        #pragma unroll
        for (int j = t; j < DD; j += THREADS) s_in[j] = __ldg(src + j);
    }
    __syncthreads();

    // static balanced row partition: block b owns [b*DD/NSM, (b+1)*DD/NSM)
    const int r_start = (int)(((long long)blockIdx.x * DD) / NSM);
    const int r_end   = (int)(((long long)(blockIdx.x + 1) * DD) / NSM);

    const int lane = t & 31;
    const int w    = t >> 5;
    const int row  = r_start + w;
    if (row >= r_end) return;   // surplus warps exit after helping the gather

    // epilogue scalars issued early (after the barrier -> no cross-sync liveness poison)
    float bv = 0.f; int sc = 0;
    if (lane == 0) {
        bv = __ldg(bias + row);
        sc = SCATTER ? __ldg(sidx + row) : row;
    }

    const float4* __restrict__ w4 = reinterpret_cast<const float4*>(W + (size_t)row * DD) + lane;
    const float4* __restrict__ s4 = reinterpret_cast<const float4*>(s_in) + lane;

    float acc0 = 0.f, acc1 = 0.f;

    if (MASK) {
        constexpr int UF = 4;                       // 4 W + 4 O float4 buffers in flight
        const float4* __restrict__ o4 = reinterpret_cast<const float4*>(O + (size_t)row * DD) + lane;
        float4 wb[UF], ob[UF];
        #pragma unroll
        for (int base = 0; base < 32; base += UF) {
            #pragma unroll
            for (int u = 0; u < UF; ++u) wb[u] = __ldcs(w4 + (base + u) * 32);
            #pragma unroll
            for (int u = 0; u < UF; ++u) ob[u] = __ldcs(o4 + (base + u) * 32);
            #pragma unroll
            for (int u = 0; u < UF; ++u) {
                const float4 xi = s4[(base + u) * 32];
                acc0 = fmaf(wb[u].x * ob[u].x, xi.x, acc0);
                acc1 = fmaf(wb[u].y * ob[u].y, xi.y, acc1);
                acc0 = fmaf(wb[u].z * ob[u].z, xi.z, acc0);
                acc1 = fmaf(wb[u].w * ob[u].w, xi.w, acc1);
            }
        }
    } else {
        constexpr int UF = 8;                       // 8 W float4 buffers in flight
        float4 wb[UF];
        #pragma unroll
        for (int base = 0; base < 32; base += UF) {
            #pragma unroll
            for (int u = 0; u < UF; ++u) wb[u] = __ldcs(w4 + (base + u) * 32);
            #pragma unroll
            for (int u = 0; u < UF; ++u) {
                const float4 xi = s4[(base + u) * 32];
                acc0 = fmaf(wb[u].x, xi.x, acc0);
                acc1 = fmaf(wb[u].y, xi.y, acc1);
                acc0 = fmaf(wb[u].z, xi.z, acc0);
                acc1 = fmaf(wb[u].w, xi.w, acc1);
            }
        }
    }

    float acc = acc0 + acc1;
    // warp tree-reduce
    #pragma unroll
    for (int off = 16; off; off >>= 1)
        acc += __shfl_down_sync(0xffffffffu, acc, off);

    if (lane == 0) dst[sc] = fmaxf(acc + bv, 0.f);
}

extern "C" void kernel_launch(void* const* d_in, const int* in_sizes, int n_in,
                              void* d_out, int out_size)
{
    const float* x       = (const float*)d_in[0];   // [D]
    const float* W_in    = (const float*)d_in[1];   // [D, D]
    const float* b_in    = (const float*)d_in[2];   // [D]
    const float* weights = (const float*)d_in[3];   // [L, D, D]
    const float* orders  = (const float*)d_in[4];   // [L, D, D]
    const float* biases  = (const float*)d_in[5];   // [L, D]
    const int*   gidx    = (const int*)d_in[6];     // [L, D]
    const int*   sidx    = (const int*)d_in[7];     // [L+1, D]
    float*       out     = (float*)d_out;           // [D]

    float *b0 = nullptr, *b1 = nullptr;
    cudaGetSymbolAddress((void**)&b0, g_buf0);
    cudaGetSymbolAddress((void**)&b1, g_buf1);

    dim3 grid(NSM), blk(THREADS);

    // input layer: relu(W_in @ x + b_in), scattered via scatter_idx[0]
    gemv_layer<false, false, true><<<grid, blk>>>(
        W_in, nullptr, b_in, x, nullptr, sidx, b0);

    // layer 0: gather g[0], masked GEMV, scatter s[1]
    gemv_layer<true, true, true><<<grid, blk>>>(
        weights, orders, biases, b0, gidx, sidx + DD, b1);

    // layer 1
    gemv_layer<true, true, true><<<grid, blk>>>(
        weights + MATSZ, orders + MATSZ, biases + DD, b1, gidx + DD, sidx + 2 * DD, b0);

    // layer 2
    gemv_layer<true, true, true><<<grid, blk>>>(
        weights + 2 * MATSZ, orders + 2 * MATSZ, biases + 2 * DD, b0, gidx + 2 * DD, sidx + 3 * DD, b1);

    // layer 3: final layer — output is the PRE-scatter activation, straight to d_out
    gemv_layer<true, true, false><<<grid, blk>>>(
        weights + 3 * MATSZ, orders + 3 * MATSZ, biases + 3 * DD, b1, gidx + 3 * DD, nullptr, out);
}